// round 14
// baseline (speedup 1.0000x reference)
#include <cuda_runtime.h>
#include <math.h>
#include <stdint.h>

#define NTOK   2048
#define DMODEL 256
#define DFF    1024
#define NHEAD  8
#define DHEAD  32
#define KWIN   5
#define NNBR   125   // 5*5*5

// ---------------- scratch (device globals; no allocations allowed) ----------
__device__ float g_q [NTOK * DMODEL];
__device__ float g_k [NTOK * DMODEL];
__device__ float g_v [NTOK * DMODEL];
__device__ float g_at[NTOK * DMODEL];
__device__ float g_h [NTOK * DMODEL];
__device__ float g_fa[NTOK * DFF];
__device__ float g_rs1[NTOK];
__device__ float g_ssp[8 * NTOK];   // per-row sumsq partials of h (8 col-slices)

// ---------------- helpers ----------------------------------------------------
__device__ __forceinline__ void mma_tf32(float d[4], const uint32_t a[4], const uint32_t b[2]) {
    asm volatile(
        "mma.sync.aligned.m16n8k8.row.col.f32.tf32.tf32.f32 "
        "{%0,%1,%2,%3},{%4,%5,%6,%7},{%8,%9},{%0,%1,%2,%3};"
        : "+f"(d[0]), "+f"(d[1]), "+f"(d[2]), "+f"(d[3])
        : "r"(a[0]), "r"(a[1]), "r"(a[2]), "r"(a[3]), "r"(b[0]), "r"(b[1]));
}

__device__ __forceinline__ void cp_async16(void* smem_dst, const void* gsrc) {
    uint32_t s = (uint32_t)__cvta_generic_to_shared(smem_dst);
    asm volatile("cp.async.cg.shared.global [%0], [%1], 16;" :: "r"(s), "l"(gsrc));
}
__device__ __forceinline__ void cp_commit() { asm volatile("cp.async.commit_group;"); }

#define ASTR 36   // A frag banks: 4g+tig -> permutation, conflict-free
#define BSTR 72   // B frag banks: 8tig+g -> permutation, conflict-free
#define NSTG 5    // pipeline stages (standard GEMM), prefetch 3 ahead
#define GSTG 4    // pipeline stages (gate), prefetch 2 ahead

// ---------------- RMS scale: one warp per token ------------------------------
__global__ __launch_bounds__(256) void rms_scale_k(const float* __restrict__ x,
                                                   float* __restrict__ rscale) {
    const int warp = threadIdx.x >> 5;
    const int lane = threadIdx.x & 31;
    const int token = blockIdx.x * 8 + warp;
    const float4 a = *(const float4*)&x[(size_t)token * DMODEL + lane * 4];
    const float4 b = *(const float4*)&x[(size_t)token * DMODEL + 128 + lane * 4];
    float s = a.x * a.x + a.y * a.y + a.z * a.z + a.w * a.w
            + b.x * b.x + b.y * b.y + b.z * b.z + b.w * b.w;
    #pragma unroll
    for (int o = 16; o; o >>= 1) s += __shfl_xor_sync(0xffffffffu, s, o);
    if (lane == 0) rscale[token] = rsqrtf(s * (1.0f / DMODEL) + 1e-6f);
}

// ---------------- TF32 GEMM v13: 32x64x32, 128 thr, 5-stage, 1 bar/iter ------
// SCALED: A_eff[m,k] = A[m,k]*rs[m]*nw[k], applied at fragment-load time.
// Optional ssp output (8 col-slices of per-row sumsq). grid.z selects triple.
template<bool SCALED>
__global__ __launch_bounds__(128) void gemm_v13(
    const float* __restrict__ A,
    const float* __restrict__ rs, const float* __restrict__ nw,
    const float* __restrict__ B0, const float* __restrict__ B1, const float* __restrict__ B2,
    const float* __restrict__ bias0, const float* __restrict__ bias1, const float* __restrict__ bias2,
    const float* __restrict__ res,
    float* __restrict__ C0, float* __restrict__ C1, float* __restrict__ C2,
    float* __restrict__ ssp,
    int N, int K) {

    const int z = blockIdx.z;
    const float* B    = (z == 0) ? B0    : (z == 1) ? B1    : B2;
    const float* bias = (z == 0) ? bias0 : (z == 1) ? bias1 : bias2;
    float*       C    = (z == 0) ? C0    : (z == 1) ? C1    : C2;

    extern __shared__ float sm[];
    float* nws = sm;                        // 256
    float* rsc = sm + DMODEL;               // 32
    float* Asm = rsc + 32;                  // NSTG * 32*ASTR
    float* Bsm = Asm + NSTG * 32 * ASTR;    // NSTG * 32*BSTR

    const int tid  = threadIdx.x;
    const int warp = tid >> 5;
    const int lane = tid & 31;
    const int g    = lane >> 2;
    const int tig  = lane & 3;
    const int warpRow = (warp & 1) * 16;
    const int warpCol = (warp >> 1) * 32;
    const int bm = blockIdx.y * 32;
    const int bn = blockIdx.x * 64;

    float sc0 = 1.f, sc1 = 1.f;
    if (SCALED) {
        for (int i = tid * 4; i < DMODEL; i += 512)
            *(float4*)&nws[i] = *(const float4*)&nw[i];
        if (tid < 32) rsc[tid] = rs[bm + tid];
    }

    float acc[4][4];
    #pragma unroll
    for (int nt = 0; nt < 4; nt++)
        #pragma unroll
        for (int i = 0; i < 4; i++) acc[nt][i] = 0.f;

    const int nkt = K >> 5;

    auto load_tile = [&](int st, int k0) {
        float* Ad = Asm + st * 32 * ASTR;
        float* Bd = Bsm + st * 32 * BSTR;
        #pragma unroll
        for (int j = 0; j < 2; j++) {          // A: 256 float4 chunks
            const int c = tid + 128 * j;
            const int row = c >> 3, kc = (c & 7) * 4;
            cp_async16(&Ad[row * ASTR + kc], &A[(size_t)(bm + row) * K + k0 + kc]);
        }
        #pragma unroll
        for (int j = 0; j < 4; j++) {          // B: 512 float4 chunks
            const int c = tid + 128 * j;
            const int row = c >> 4, nc = (c & 15) * 4;
            cp_async16(&Bd[row * BSTR + nc], &B[(size_t)(k0 + row) * N + bn + nc]);
        }
        cp_commit();
    };

    load_tile(0, 0);
    load_tile(1, 32);
    load_tile(2, 64);

    if (SCALED) {
        __syncthreads();                      // rsc/nws visible
        sc0 = rsc[warpRow + g];
        sc1 = rsc[warpRow + g + 8];
    }

    for (int kt = 0; kt < nkt; kt++) {
        const int st = kt % NSTG;
        if (kt + 3 < nkt) load_tile((kt + 3) % NSTG, (kt + 3) * 32);
        if (kt + 3 < nkt)      asm volatile("cp.async.wait_group 3;");
        else if (kt + 2 < nkt) asm volatile("cp.async.wait_group 2;");
        else if (kt + 1 < nkt) asm volatile("cp.async.wait_group 1;");
        else                   asm volatile("cp.async.wait_group 0;");
        __syncthreads();                      // single barrier per iteration

        const float* Ab = Asm + st * 32 * ASTR;
        const float* Bb = Bsm + st * 32 * BSTR;
        const int kb = kt * 32;
        #pragma unroll
        for (int s = 0; s < 4; s++) {
            const int r0 = warpRow + g;
            float a0 = Ab[r0 * ASTR + 8 * s + tig];
            float a1 = Ab[(r0 + 8) * ASTR + 8 * s + tig];
            float a2 = Ab[r0 * ASTR + 8 * s + 4 + tig];
            float a3 = Ab[(r0 + 8) * ASTR + 8 * s + 4 + tig];
            if (SCALED) {
                const float w0 = nws[kb + 8 * s + tig];
                const float w1 = nws[kb + 8 * s + 4 + tig];
                a0 *= sc0 * w0; a1 *= sc1 * w0; a2 *= sc0 * w1; a3 *= sc1 * w1;
            }
            uint32_t ua[4] = {__float_as_uint(a0), __float_as_uint(a1),
                              __float_as_uint(a2), __float_as_uint(a3)};
            uint32_t b[4][2];
            #pragma unroll
            for (int nt = 0; nt < 4; nt++) {
                const int c = warpCol + nt * 8 + g;
                b[nt][0] = __float_as_uint(Bb[(8 * s + tig) * BSTR + c]);
                b[nt][1] = __float_as_uint(Bb[(8 * s + 4 + tig) * BSTR + c]);
            }
            #pragma unroll
            for (int nt = 0; nt < 4; nt++) mma_tf32(acc[nt], ua, b[nt]);
        }
        // no trailing barrier: writer stage (kt+3)%NSTG never aliases any
        // stage readable by a warp at iteration kt or kt-1 (NSTG=5 > 3+1)
    }

    // epilogue (+optional per-row sumsq partials for the next rmsnorm)
    const int r0 = bm + warpRow + g;
    const int r1 = r0 + 8;
    float s0 = 0.f, s1 = 0.f;
    #pragma unroll
    for (int nt = 0; nt < 4; nt++) {
        const int col = bn + warpCol + nt * 8 + 2 * tig;
        float b0 = 0.f, b1 = 0.f;
        if (bias) { b0 = bias[col]; b1 = bias[col + 1]; }
        float2 o0 = make_float2(acc[nt][0] + b0, acc[nt][1] + b1);
        float2 o1 = make_float2(acc[nt][2] + b0, acc[nt][3] + b1);
        if (res) {
            const float2 q0 = *(const float2*)&res[(size_t)r0 * N + col];
            const float2 q1 = *(const float2*)&res[(size_t)r1 * N + col];
            o0.x += q0.x; o0.y += q0.y;
            o1.x += q1.x; o1.y += q1.y;
        }
        s0 += o0.x * o0.x + o0.y * o0.y;
        s1 += o1.x * o1.x + o1.y * o1.y;
        *(float2*)&C[(size_t)r0 * N + col] = o0;
        *(float2*)&C[(size_t)r1 * N + col] = o1;
    }
    if (ssp) {
        s0 += __shfl_xor_sync(0xffffffffu, s0, 1);
        s0 += __shfl_xor_sync(0xffffffffu, s0, 2);
        s1 += __shfl_xor_sync(0xffffffffu, s1, 1);
        s1 += __shfl_xor_sync(0xffffffffu, s1, 2);
        if (tig == 0) {
            const int p = blockIdx.x * 2 + (warp >> 1);   // 0..7 distinct col slices
            ssp[p * NTOK + r0] = s0;
            ssp[p * NTOK + r1] = s1;
        }
    }
}

// ---------------- gate GEMM v13: 32x64x32, dual B, 4-stage, 1 bar/iter -------
// silu(A'@W1)*(A'@W2); A' = rmsnorm(A), row scale from 8 sumsq partials.
__global__ __launch_bounds__(128) void gate_v13(
    const float* __restrict__ A,
    const float* __restrict__ ssp, const float* __restrict__ nw,
    const float* __restrict__ W1, const float* __restrict__ W2,
    float* __restrict__ C, int N, int K) {

    extern __shared__ float dsm[];
    float* nws = dsm;                       // 256
    float* rsc = dsm + DMODEL;              // 32
    float* Asm = rsc + 32;                  // GSTG * 32*ASTR
    float* B1m = Asm + GSTG * 32 * ASTR;    // GSTG * 32*BSTR
    float* B2m = B1m + GSTG * 32 * BSTR;    // GSTG * 32*BSTR

    const int tid  = threadIdx.x;
    const int warp = tid >> 5;
    const int lane = tid & 31;
    const int g    = lane >> 2;
    const int tig  = lane & 3;
    const int warpRow = (warp & 1) * 16;
    const int warpCol = (warp >> 1) * 32;
    const int bm = blockIdx.y * 32;
    const int bn = blockIdx.x * 64;

    for (int i = tid * 4; i < DMODEL; i += 512)
        *(float4*)&nws[i] = *(const float4*)&nw[i];
    if (tid < 32) {
        const int row = bm + tid;
        float s = 0.f;
        #pragma unroll
        for (int p = 0; p < 8; p++) s += ssp[p * NTOK + row];
        rsc[tid] = rsqrtf(s * (1.0f / DMODEL) + 1e-6f);
    }

    float acc1[4][4], acc2[4][4];
    #pragma unroll
    for (int nt = 0; nt < 4; nt++)
        #pragma unroll
        for (int i = 0; i < 4; i++) { acc1[nt][i] = 0.f; acc2[nt][i] = 0.f; }

    const int nkt = K >> 5;

    auto load_tile = [&](int st, int k0) {
        float* Ad  = Asm + st * 32 * ASTR;
        float* B1d = B1m + st * 32 * BSTR;
        float* B2d = B2m + st * 32 * BSTR;
        #pragma unroll
        for (int j = 0; j < 2; j++) {
            const int c = tid + 128 * j;
            const int row = c >> 3, kc = (c & 7) * 4;
            cp_async16(&Ad[row * ASTR + kc], &A[(size_t)(bm + row) * K + k0 + kc]);
        }
        #pragma unroll
        for (int j = 0; j < 4; j++) {
            const int c = tid + 128 * j;
            const int row = c >> 4, nc = (c & 15) * 4;
            const size_t off = (size_t)(k0 + row) * N + bn + nc;
            cp_async16(&B1d[row * BSTR + nc], &W1[off]);
            cp_async16(&B2d[row * BSTR + nc], &W2[off]);
        }
        cp_commit();
    };

    load_tile(0, 0);
    load_tile(1, 32);

    __syncthreads();                          // rsc/nws visible
    const float sc0 = rsc[warpRow + g];
    const float sc1 = rsc[warpRow + g + 8];

    for (int kt = 0; kt < nkt; kt++) {
        const int st = kt % GSTG;
        if (kt + 2 < nkt) load_tile((kt + 2) % GSTG, (kt + 2) * 32);
        if (kt + 2 < nkt)      asm volatile("cp.async.wait_group 2;");
        else if (kt + 1 < nkt) asm volatile("cp.async.wait_group 1;");
        else                   asm volatile("cp.async.wait_group 0;");
        __syncthreads();                      // single barrier per iteration

        const float* Ab  = Asm + st * 32 * ASTR;
        const float* B1b = B1m + st * 32 * BSTR;
        const float* B2b = B2m + st * 32 * BSTR;
        const int kb = kt * 32;
        #pragma unroll
        for (int s = 0; s < 4; s++) {
            const int r0 = warpRow + g;
            float a0 = Ab[r0 * ASTR + 8 * s + tig];
            float a1 = Ab[(r0 + 8) * ASTR + 8 * s + tig];
            float a2 = Ab[r0 * ASTR + 8 * s + 4 + tig];
            float a3 = Ab[(r0 + 8) * ASTR + 8 * s + 4 + tig];
            const float w0 = nws[kb + 8 * s + tig];
            const float w1 = nws[kb + 8 * s + 4 + tig];
            a0 *= sc0 * w0; a1 *= sc1 * w0; a2 *= sc0 * w1; a3 *= sc1 * w1;
            uint32_t ua[4] = {__float_as_uint(a0), __float_as_uint(a1),
                              __float_as_uint(a2), __float_as_uint(a3)};
            uint32_t b1[4][2], b2[4][2];
            #pragma unroll
            for (int nt = 0; nt < 4; nt++) {
                const int c = warpCol + nt * 8 + g;
                b1[nt][0] = __float_as_uint(B1b[(8 * s + tig) * BSTR + c]);
                b1[nt][1] = __float_as_uint(B1b[(8 * s + 4 + tig) * BSTR + c]);
                b2[nt][0] = __float_as_uint(B2b[(8 * s + tig) * BSTR + c]);
                b2[nt][1] = __float_as_uint(B2b[(8 * s + 4 + tig) * BSTR + c]);
            }
            #pragma unroll
            for (int nt = 0; nt < 4; nt++) {
                mma_tf32(acc1[nt], ua, b1[nt]);
                mma_tf32(acc2[nt], ua, b2[nt]);
            }
        }
        // no trailing barrier (GSTG=4 > 2+1)
    }

    const int r0 = bm + warpRow + g;
    const int r1 = r0 + 8;
    #pragma unroll
    for (int nt = 0; nt < 4; nt++) {
        const int col = bn + warpCol + nt * 8 + 2 * tig;
        #pragma unroll
        for (int half = 0; half < 2; half++) {
            const int row = (half == 0) ? r0 : r1;
            const float a0 = acc1[nt][half * 2 + 0];
            const float a1 = acc1[nt][half * 2 + 1];
            float2 o;
            o.x = a0 / (1.f + __expf(-a0)) * acc2[nt][half * 2 + 0];
            o.y = a1 / (1.f + __expf(-a1)) * acc2[nt][half * 2 + 1];
            *(float2*)&C[(size_t)row * N + col] = o;
        }
    }
}

// ---------------- NA3D attention: smem-tiled ---------------------------------
__global__ __launch_bounds__(512) void na3d_k(
    const float* __restrict__ q, const float* __restrict__ k,
    const float* __restrict__ v, float* __restrict__ out) {

    __shared__ float smk[320 * 32];
    __shared__ int   nbase[128];

    const int tile = blockIdx.x;
    const int head = blockIdx.y;
    const int t  = tile >> 4;
    const int hh = (tile >> 2) & 3;
    const int ww = tile & 3;
    const int tile_h0 = hh * 4, tile_w0 = ww * 4;
    const int h_base = min(max(tile_h0 - 2, 0), 8);
    const int w_base = min(max(tile_w0 - 2, 0), 8);

    const int tid  = threadIdx.x;
    const int warp = tid >> 5;
    const int lane = tid & 31;
    const int g    = lane >> 3;
    const int sub  = lane & 7;

    if (tid < 128) {
        const int m = tid;
        int val;
        if (m < NNBR) {
            const int mt = m / 25;
            const int mh = (m / 5) % 5;
            const int mw = m % 5;
            val = (mt * 64 + mh * 8 + mw) | (mt << 16);
        } else {
            val = (-8) << 16;
        }
        nbase[tid] = val;
    }

    const int h = tile_h0 + (warp >> 2);
    const int w = tile_w0 + (warp & 3);
    const int token = (t * 16 + h) * 16 + w;
    const int hoff = min(max(h - 2, 0), 11) - h_base;
    const int woff = min(max(w - 2, 0), 11) - w_base;
    const int sbase = hoff * 8 + woff;

    #pragma unroll
    for (int j = 0; j < 5; j++) {
        const int c = tid + 512 * j;
        const int slot = c >> 3, s8 = c & 7;
        const int tl = slot >> 6, rem = slot & 63;
        const int tn = max(t - 4 + tl, 0);
        const int hn = h_base + (rem >> 3), wn = w_base + (rem & 7);
        const float4 kv = *(const float4*)&k[(size_t)((tn * 16 + hn) * 16 + wn) * DMODEL + head * DHEAD + s8 * 4];
        *(float4*)&smk[slot * 32 + s8 * 4] = kv;
    }
    const float4 q4 = *(const float4*)&q[(size_t)token * DMODEL + head * DHEAD + sub * 4];
    __syncthreads();

    float lg[32];
    const float scale = 0.17677669529663687f;
    #pragma unroll
    for (int i = 0; i < 32; i++) {
        const int m   = i * 4 + g;
        const int val = nbase[m];
        const int slot = (val & 0xFFFF) + sbase;
        const int mt   = val >> 16;
        const float4 kv = *(const float4*)&smk[slot * 32 + sub * 4];
        float d = q4.x * kv.x + q4.y * kv.y + q4.z * kv.z + q4.w * kv.w;
        d += __shfl_xor_sync(0xffffffffu, d, 1);
        d += __shfl_xor_sync(0xffffffffu, d, 2);
        d += __shfl_xor_sync(0xffffffffu, d, 4);
        lg[i] = (t - 4 + mt >= 0) ? d * scale : -INFINITY;
    }

    float mx = -INFINITY;
    #pragma unroll
    for (int i = 0; i < 32; i++) mx = fmaxf(mx, lg[i]);
    #pragma unroll
    for (int o = 16; o; o >>= 1) mx = fmaxf(mx, __shfl_xor_sync(0xffffffffu, mx, o));
    float sum = 0.f;
    #pragma unroll
    for (int i = 0; i < 32; i++) { lg[i] = __expf(lg[i] - mx); sum += lg[i]; }
    sum += __shfl_xor_sync(0xffffffffu, sum, 8);
    sum += __shfl_xor_sync(0xffffffffu, sum, 16);
    const float inv = 1.f / sum;

    __syncthreads();
    #pragma unroll
    for (int j = 0; j < 5; j++) {
        const int c = tid + 512 * j;
        const int slot = c >> 3, s8 = c & 7;
        const int tl = slot >> 6, rem = slot & 63;
        const int tn = max(t - 4 + tl, 0);
        const int hn = h_base + (rem >> 3), wn = w_base + (rem & 7);
        const float4 vv = *(const float4*)&v[(size_t)((tn * 16 + hn) * 16 + wn) * DMODEL + head * DHEAD + s8 * 4];
        *(float4*)&smk[slot * 32 + s8 * 4] = vv;
    }
    __syncthreads();

    float4 acc = make_float4(0.f, 0.f, 0.f, 0.f);
    #pragma unroll
    for (int i = 0; i < 32; i++) {
        const int m    = i * 4 + g;
        const int slot = (nbase[m] & 0xFFFF) + sbase;
        const float4 vv = *(const float4*)&smk[slot * 32 + sub * 4];
        const float p = lg[i];
        acc.x = fmaf(p, vv.x, acc.x);
        acc.y = fmaf(p, vv.y, acc.y);
        acc.z = fmaf(p, vv.z, acc.z);
        acc.w = fmaf(p, vv.w, acc.w);
    }
    #pragma unroll
    for (int o = 8; o <= 16; o <<= 1) {
        acc.x += __shfl_xor_sync(0xffffffffu, acc.x, o);
        acc.y += __shfl_xor_sync(0xffffffffu, acc.y, o);
        acc.z += __shfl_xor_sync(0xffffffffu, acc.z, o);
        acc.w += __shfl_xor_sync(0xffffffffu, acc.w, o);
    }
    if (g == 0) {
        float4 o4 = make_float4(acc.x * inv, acc.y * inv, acc.z * inv, acc.w * inv);
        *(float4*)&out[(size_t)token * DMODEL + head * DHEAD + sub * 4] = o4;
    }
}

// ---------------- launch ------------------------------------------------------
extern "C" void kernel_launch(void* const* d_in, const int* in_sizes, int n_in,
                              void* d_out, int out_size) {
    const float* x   = (const float*)d_in[0];
    const float* n1w = (const float*)d_in[1];
    const float* n2w = (const float*)d_in[2];
    const float* wq  = (const float*)d_in[3];
    const float* bq  = (const float*)d_in[4];
    const float* wk  = (const float*)d_in[5];
    const float* bk  = (const float*)d_in[6];
    const float* wv  = (const float*)d_in[7];
    const float* bv  = (const float*)d_in[8];
    const float* wo  = (const float*)d_in[9];
    const float* bo  = (const float*)d_in[10];
    const float* w1  = (const float*)d_in[11];
    const float* w2  = (const float*)d_in[12];
    const float* w3  = (const float*)d_in[13];
    float* out = (float*)d_out;

    float *p_q, *p_k, *p_v, *p_at, *p_h, *p_fa, *p_rs1, *p_ssp;
    cudaGetSymbolAddress((void**)&p_q,  g_q);
    cudaGetSymbolAddress((void**)&p_k,  g_k);
    cudaGetSymbolAddress((void**)&p_v,  g_v);
    cudaGetSymbolAddress((void**)&p_at, g_at);
    cudaGetSymbolAddress((void**)&p_h,  g_h);
    cudaGetSymbolAddress((void**)&p_fa, g_fa);
    cudaGetSymbolAddress((void**)&p_rs1, g_rs1);
    cudaGetSymbolAddress((void**)&p_ssp, g_ssp);

    const int gemm_smem = (DMODEL + 32 + NSTG * 32 * ASTR + NSTG * 32 * BSTR) * 4;     // 70272
    const int gate_smem = (DMODEL + 32 + GSTG * 32 * ASTR + 2 * GSTG * 32 * BSTR) * 4; // 93312
    static int configured = 0;
    if (!configured) {
        cudaFuncSetAttribute(gemm_v13<true>,  cudaFuncAttributeMaxDynamicSharedMemorySize, gemm_smem);
        cudaFuncSetAttribute(gemm_v13<false>, cudaFuncAttributeMaxDynamicSharedMemorySize, gemm_smem);
        cudaFuncSetAttribute(gate_v13, cudaFuncAttributeMaxDynamicSharedMemorySize, gate_smem);
        configured = 1;
    }

    const dim3 blk(128);

    // 1) rscale1 = rms scale of x
    rms_scale_k<<<NTOK / 8, 256>>>(x, p_rs1);

    // 2) q,k,v = rmsnorm(x) @ {wq,wk,wv} + bias
    gemm_v13<true><<<dim3(DMODEL / 64, NTOK / 32, 3), blk, gemm_smem>>>(
        x, p_rs1, n1w, wq, wk, wv, bq, bk, bv, nullptr,
        p_q, p_k, p_v, nullptr, DMODEL, DMODEL);

    // 3) neighborhood attention
    na3d_k<<<dim3(128, NHEAD), 512>>>(p_q, p_k, p_v, p_at);

    // 4) h = x + attn @ wo + bo   (+ per-row sumsq partials of h)
    gemm_v13<false><<<dim3(DMODEL / 64, NTOK / 32, 1), blk, gemm_smem>>>(
        p_at, nullptr, nullptr, wo, nullptr, nullptr, bo, nullptr, nullptr, x,
        p_h, nullptr, nullptr, p_ssp, DMODEL, DMODEL);

    // 5) fa = silu(rmsnorm(h)@w1) * (rmsnorm(h)@w2)  (rms scale from partials)
    gate_v13<<<dim3(DFF / 64, NTOK / 32), blk, gate_smem>>>(
        p_h, p_ssp, n2w, w1, w2, p_fa, DFF, DMODEL);

    // 6) out = h + fa @ w3
    gemm_v13<false><<<dim3(DMODEL / 64, NTOK / 32, 1), blk, gemm_smem>>>(
        p_fa, nullptr, nullptr, w3, nullptr, nullptr, nullptr, nullptr, nullptr, p_h,
        out, nullptr, nullptr, nullptr, DMODEL, DFF);
}

// round 15
// speedup vs baseline: 1.2429x; 1.2429x over previous
#include <cuda_runtime.h>
#include <math.h>
#include <stdint.h>

#define NTOK   2048
#define DMODEL 256
#define DFF    1024
#define NHEAD  8
#define DHEAD  32
#define KWIN   5
#define NNBR   125   // 5*5*5

// ---------------- scratch (device globals; no allocations allowed) ----------
__device__ float g_q [NTOK * DMODEL];
__device__ float g_k [NTOK * DMODEL];
__device__ float g_v [NTOK * DMODEL];
__device__ float g_at[NTOK * DMODEL];
__device__ float g_h [NTOK * DMODEL];
__device__ float g_fa[NTOK * DFF];
__device__ float g_rs1[NTOK];
__device__ float g_ssp[8 * NTOK];   // per-row sumsq partials of h (8 col-slices)

// ---------------- helpers ----------------------------------------------------
__device__ __forceinline__ void mma_tf32(float d[4], const uint32_t a[4], const uint32_t b[2]) {
    asm volatile(
        "mma.sync.aligned.m16n8k8.row.col.f32.tf32.tf32.f32 "
        "{%0,%1,%2,%3},{%4,%5,%6,%7},{%8,%9},{%0,%1,%2,%3};"
        : "+f"(d[0]), "+f"(d[1]), "+f"(d[2]), "+f"(d[3])
        : "r"(a[0]), "r"(a[1]), "r"(a[2]), "r"(a[3]), "r"(b[0]), "r"(b[1]));
}

__device__ __forceinline__ void cp_async16(void* smem_dst, const void* gsrc) {
    uint32_t s = (uint32_t)__cvta_generic_to_shared(smem_dst);
    asm volatile("cp.async.cg.shared.global [%0], [%1], 16;" :: "r"(s), "l"(gsrc));
}
__device__ __forceinline__ void cp_commit() { asm volatile("cp.async.commit_group;"); }

#define ASTR 36   // A frag banks: 4g+tig -> permutation, conflict-free
#define BSTR 72   // B frag banks: 8tig+g -> permutation, conflict-free
#define NSTG 3    // pipeline stages

// ---------------- RMS scale: one warp per token ------------------------------
__global__ __launch_bounds__(256) void rms_scale_k(const float* __restrict__ x,
                                                   float* __restrict__ rscale) {
    const int warp = threadIdx.x >> 5;
    const int lane = threadIdx.x & 31;
    const int token = blockIdx.x * 8 + warp;
    const float4 a = *(const float4*)&x[(size_t)token * DMODEL + lane * 4];
    const float4 b = *(const float4*)&x[(size_t)token * DMODEL + 128 + lane * 4];
    float s = a.x * a.x + a.y * a.y + a.z * a.z + a.w * a.w
            + b.x * b.x + b.y * b.y + b.z * b.z + b.w * b.w;
    #pragma unroll
    for (int o = 16; o; o >>= 1) s += __shfl_xor_sync(0xffffffffu, s, o);
    if (lane == 0) rscale[token] = rsqrtf(s * (1.0f / DMODEL) + 1e-6f);
}

// ---------------- TF32 GEMM v7: 32x64x32, 128 thr, 3-stage, conflict-free ----
template<bool SCALED>
__global__ __launch_bounds__(128) void gemm_v7(
    const float* __restrict__ A,
    const float* __restrict__ rs, const float* __restrict__ nw,
    const float* __restrict__ B0, const float* __restrict__ B1, const float* __restrict__ B2,
    const float* __restrict__ bias0, const float* __restrict__ bias1, const float* __restrict__ bias2,
    const float* __restrict__ res,
    float* __restrict__ C0, float* __restrict__ C1, float* __restrict__ C2,
    float* __restrict__ ssp,
    int N, int K) {

    const int z = blockIdx.z;
    const float* B    = (z == 0) ? B0    : (z == 1) ? B1    : B2;
    const float* bias = (z == 0) ? bias0 : (z == 1) ? bias1 : bias2;
    float*       C    = (z == 0) ? C0    : (z == 1) ? C1    : C2;

    __shared__ float As[NSTG][32 * ASTR];
    __shared__ float Bs[NSTG][32 * BSTR];
    __shared__ float nws[DMODEL];
    __shared__ float rsc[32];

    const int tid  = threadIdx.x;
    const int warp = tid >> 5;
    const int lane = tid & 31;
    const int g    = lane >> 2;
    const int tig  = lane & 3;
    const int warpRow = (warp & 1) * 16;
    const int warpCol = (warp >> 1) * 32;
    const int bm = blockIdx.y * 32;
    const int bn = blockIdx.x * 64;

    float sc0 = 1.f, sc1 = 1.f;
    if (SCALED) {
        for (int i = tid * 4; i < K; i += 512)
            *(float4*)&nws[i] = *(const float4*)&nw[i];
        if (tid < 32) rsc[tid] = rs[bm + tid];
        __syncthreads();
        sc0 = rsc[warpRow + g];
        sc1 = rsc[warpRow + g + 8];
    }

    float acc[4][4];
    #pragma unroll
    for (int nt = 0; nt < 4; nt++)
        #pragma unroll
        for (int i = 0; i < 4; i++) acc[nt][i] = 0.f;

    const int nkt = K >> 5;

    auto load_tile = [&](int st, int k0) {
        #pragma unroll
        for (int j = 0; j < 2; j++) {
            const int c = tid + 128 * j;
            const int row = c >> 3, kc = (c & 7) * 4;
            cp_async16(&As[st][row * ASTR + kc], &A[(size_t)(bm + row) * K + k0 + kc]);
        }
        #pragma unroll
        for (int j = 0; j < 4; j++) {
            const int c = tid + 128 * j;
            const int row = c >> 4, nc = (c & 15) * 4;
            cp_async16(&Bs[st][row * BSTR + nc], &B[(size_t)(k0 + row) * N + bn + nc]);
        }
        cp_commit();
    };

    load_tile(0, 0);
    load_tile(1, 32);

    for (int kt = 0; kt < nkt; kt++) {
        const int st = kt % NSTG;
        if (kt + 2 < nkt) load_tile((kt + 2) % NSTG, (kt + 2) * 32);
        if (kt + 2 < nkt)      asm volatile("cp.async.wait_group 2;");
        else if (kt + 1 < nkt) asm volatile("cp.async.wait_group 1;");
        else                   asm volatile("cp.async.wait_group 0;");
        __syncthreads();

        const float* Ab = As[st];
        const float* Bb = Bs[st];
        const int kb = kt * 32;
        #pragma unroll
        for (int s = 0; s < 4; s++) {
            const int r0 = warpRow + g;
            float a0 = Ab[r0 * ASTR + 8 * s + tig];
            float a1 = Ab[(r0 + 8) * ASTR + 8 * s + tig];
            float a2 = Ab[r0 * ASTR + 8 * s + 4 + tig];
            float a3 = Ab[(r0 + 8) * ASTR + 8 * s + 4 + tig];
            if (SCALED) {
                const float w0 = nws[kb + 8 * s + tig];
                const float w1 = nws[kb + 8 * s + 4 + tig];
                a0 *= sc0 * w0; a1 *= sc1 * w0; a2 *= sc0 * w1; a3 *= sc1 * w1;
            }
            uint32_t ua[4] = {__float_as_uint(a0), __float_as_uint(a1),
                              __float_as_uint(a2), __float_as_uint(a3)};
            uint32_t b[4][2];
            #pragma unroll
            for (int nt = 0; nt < 4; nt++) {
                const int c = warpCol + nt * 8 + g;
                b[nt][0] = __float_as_uint(Bb[(8 * s + tig) * BSTR + c]);
                b[nt][1] = __float_as_uint(Bb[(8 * s + 4 + tig) * BSTR + c]);
            }
            #pragma unroll
            for (int nt = 0; nt < 4; nt++) mma_tf32(acc[nt], ua, b[nt]);
        }
        __syncthreads();
    }

    const int r0 = bm + warpRow + g;
    const int r1 = r0 + 8;
    float s0 = 0.f, s1 = 0.f;
    #pragma unroll
    for (int nt = 0; nt < 4; nt++) {
        const int col = bn + warpCol + nt * 8 + 2 * tig;
        float b0 = 0.f, b1 = 0.f;
        if (bias) { b0 = bias[col]; b1 = bias[col + 1]; }
        float2 o0 = make_float2(acc[nt][0] + b0, acc[nt][1] + b1);
        float2 o1 = make_float2(acc[nt][2] + b0, acc[nt][3] + b1);
        if (res) {
            const float2 q0 = *(const float2*)&res[(size_t)r0 * N + col];
            const float2 q1 = *(const float2*)&res[(size_t)r1 * N + col];
            o0.x += q0.x; o0.y += q0.y;
            o1.x += q1.x; o1.y += q1.y;
        }
        s0 += o0.x * o0.x + o0.y * o0.y;
        s1 += o1.x * o1.x + o1.y * o1.y;
        *(float2*)&C[(size_t)r0 * N + col] = o0;
        *(float2*)&C[(size_t)r1 * N + col] = o1;
    }
    if (ssp) {
        s0 += __shfl_xor_sync(0xffffffffu, s0, 1);
        s0 += __shfl_xor_sync(0xffffffffu, s0, 2);
        s1 += __shfl_xor_sync(0xffffffffu, s1, 1);
        s1 += __shfl_xor_sync(0xffffffffu, s1, 2);
        if (tig == 0) {
            const int p = blockIdx.x * 2 + (warp >> 1);
            ssp[p * NTOK + r0] = s0;
            ssp[p * NTOK + r1] = s1;
        }
    }
}

// ---------------- gate GEMM v7: silu(A'@W1)*(A'@W2), 3-stage, dual B ---------
__global__ __launch_bounds__(128) void gate_v7(
    const float* __restrict__ A,
    const float* __restrict__ ssp, const float* __restrict__ nw,
    const float* __restrict__ W1, const float* __restrict__ W2,
    float* __restrict__ C, int N, int K) {

    extern __shared__ float dsm[];
    float* nws = dsm;
    float* rsc = dsm + DMODEL;
    float* Asm = rsc + 32;
    float* B1m = Asm + NSTG * 32 * ASTR;
    float* B2m = B1m + NSTG * 32 * BSTR;

    const int tid  = threadIdx.x;
    const int warp = tid >> 5;
    const int lane = tid & 31;
    const int g    = lane >> 2;
    const int tig  = lane & 3;
    const int warpRow = (warp & 1) * 16;
    const int warpCol = (warp >> 1) * 32;
    const int bm = blockIdx.y * 32;
    const int bn = blockIdx.x * 64;

    for (int i = tid * 4; i < K; i += 512)
        *(float4*)&nws[i] = *(const float4*)&nw[i];
    if (tid < 32) {
        const int row = bm + tid;
        float s = 0.f;
        #pragma unroll
        for (int p = 0; p < 8; p++) s += ssp[p * NTOK + row];
        rsc[tid] = rsqrtf(s * (1.0f / DMODEL) + 1e-6f);
    }
    __syncthreads();
    const float sc0 = rsc[warpRow + g];
    const float sc1 = rsc[warpRow + g + 8];

    float acc1[4][4], acc2[4][4];
    #pragma unroll
    for (int nt = 0; nt < 4; nt++)
        #pragma unroll
        for (int i = 0; i < 4; i++) { acc1[nt][i] = 0.f; acc2[nt][i] = 0.f; }

    const int nkt = K >> 5;

    auto load_tile = [&](int st, int k0) {
        float* Ad  = Asm + st * 32 * ASTR;
        float* B1d = B1m + st * 32 * BSTR;
        float* B2d = B2m + st * 32 * BSTR;
        #pragma unroll
        for (int j = 0; j < 2; j++) {
            const int c = tid + 128 * j;
            const int row = c >> 3, kc = (c & 7) * 4;
            cp_async16(&Ad[row * ASTR + kc], &A[(size_t)(bm + row) * K + k0 + kc]);
        }
        #pragma unroll
        for (int j = 0; j < 4; j++) {
            const int c = tid + 128 * j;
            const int row = c >> 4, nc = (c & 15) * 4;
            const size_t off = (size_t)(k0 + row) * N + bn + nc;
            cp_async16(&B1d[row * BSTR + nc], &W1[off]);
            cp_async16(&B2d[row * BSTR + nc], &W2[off]);
        }
        cp_commit();
    };

    load_tile(0, 0);
    load_tile(1, 32);

    for (int kt = 0; kt < nkt; kt++) {
        const int st = kt % NSTG;
        if (kt + 2 < nkt) load_tile((kt + 2) % NSTG, (kt + 2) * 32);
        if (kt + 2 < nkt)      asm volatile("cp.async.wait_group 2;");
        else if (kt + 1 < nkt) asm volatile("cp.async.wait_group 1;");
        else                   asm volatile("cp.async.wait_group 0;");
        __syncthreads();

        const float* Ab  = Asm + st * 32 * ASTR;
        const float* B1b = B1m + st * 32 * BSTR;
        const float* B2b = B2m + st * 32 * BSTR;
        const int kb = kt * 32;
        #pragma unroll
        for (int s = 0; s < 4; s++) {
            const int r0 = warpRow + g;
            float a0 = Ab[r0 * ASTR + 8 * s + tig];
            float a1 = Ab[(r0 + 8) * ASTR + 8 * s + tig];
            float a2 = Ab[r0 * ASTR + 8 * s + 4 + tig];
            float a3 = Ab[(r0 + 8) * ASTR + 8 * s + 4 + tig];
            const float w0 = nws[kb + 8 * s + tig];
            const float w1 = nws[kb + 8 * s + 4 + tig];
            a0 *= sc0 * w0; a1 *= sc1 * w0; a2 *= sc0 * w1; a3 *= sc1 * w1;
            uint32_t ua[4] = {__float_as_uint(a0), __float_as_uint(a1),
                              __float_as_uint(a2), __float_as_uint(a3)};
            uint32_t b1[4][2], b2[4][2];
            #pragma unroll
            for (int nt = 0; nt < 4; nt++) {
                const int c = warpCol + nt * 8 + g;
                b1[nt][0] = __float_as_uint(B1b[(8 * s + tig) * BSTR + c]);
                b1[nt][1] = __float_as_uint(B1b[(8 * s + 4 + tig) * BSTR + c]);
                b2[nt][0] = __float_as_uint(B2b[(8 * s + tig) * BSTR + c]);
                b2[nt][1] = __float_as_uint(B2b[(8 * s + 4 + tig) * BSTR + c]);
            }
            #pragma unroll
            for (int nt = 0; nt < 4; nt++) {
                mma_tf32(acc1[nt], ua, b1[nt]);
                mma_tf32(acc2[nt], ua, b2[nt]);
            }
        }
        __syncthreads();
    }

    const int r0 = bm + warpRow + g;
    const int r1 = r0 + 8;
    #pragma unroll
    for (int nt = 0; nt < 4; nt++) {
        const int col = bn + warpCol + nt * 8 + 2 * tig;
        #pragma unroll
        for (int half = 0; half < 2; half++) {
            const int row = (half == 0) ? r0 : r1;
            const float a0 = acc1[nt][half * 2 + 0];
            const float a1 = acc1[nt][half * 2 + 1];
            float2 o;
            o.x = a0 / (1.f + __expf(-a0)) * acc2[nt][half * 2 + 0];
            o.y = a1 / (1.f + __expf(-a1)) * acc2[nt][half * 2 + 1];
            *(float2*)&C[(size_t)row * N + col] = o;
        }
    }
}

// ---------------- NA3D v3: tensor-core attention ------------------------------
// Block = (4x4 spatial tile, t-slice) x head, 256 threads (8 warps).
// S^T = K(320x32) @ Q^T(32x16) via mma; masked softmax; O = P(16x320) @ V(320x32).
#define KVSTR 36   // K/V row stride: frag banks 4s+c -> permutation
#define PSTR  324  // P row stride: 324%32=4 -> frag banks 4g+tig / stores 8tig+g

__global__ __launch_bounds__(256) void na3d_v3(
    const float* __restrict__ q, const float* __restrict__ k,
    const float* __restrict__ v, float* __restrict__ out) {

    extern __shared__ float sm[];
    float* KV   = sm;                   // 320*36 = 11520
    float* Psm  = KV + 320 * KVSTR;     // 16*324 = 5184
    float* Qsm  = Psm + 16 * PSTR;      // 16*36  = 576
    float* red  = Qsm + 16 * KVSTR;     // 16*8   = 128
    float* Gm   = red + 128;            // 16
    float* Ssum = Gm + 16;              // 16
    float* redO = Ssum + 16;            // 512
    int*  rinfo = (int*)(redO + 512);   // 16

    const int tile = blockIdx.x, head = blockIdx.y;
    const int t  = tile >> 4;
    const int th0 = ((tile >> 2) & 3) * 4;
    const int tw0 = (tile & 3) * 4;
    const int h_base = min(max(th0 - 2, 0), 8);
    const int w_base = min(max(tw0 - 2, 0), 8);
    const int tlmin  = max(0, 4 - t);
    const float scale = 0.17677669529663687f;   // 1/sqrt(32)

    const int tid = threadIdx.x;
    const int wp  = tid >> 5;
    const int l   = tid & 31;
    const int gr  = l >> 2;
    const int tig = l & 3;

    // ---- stage Q, row info, K ----
    if (tid < 16) {
        const int hr = th0 + (tid >> 2), wr = tw0 + (tid & 3);
        const int hoff = min(max(hr - 2, 0), 11) - h_base;
        const int woff = min(max(wr - 2, 0), 11) - w_base;
        const int tok  = (t * 16 + hr) * 16 + wr;
        rinfo[tid] = hoff | (woff << 4) | (tok << 8);
    }
    if (tid < 128) {
        const int r = tid >> 3, c4 = (tid & 7) * 4;
        const int hr = th0 + (r >> 2), wr = tw0 + (r & 3);
        const int tok = (t * 16 + hr) * 16 + wr;
        *(float4*)&Qsm[r * KVSTR + c4] =
            *(const float4*)&q[(size_t)tok * DMODEL + head * DHEAD + c4];
    }
    #pragma unroll
    for (int j = 0; j < 10; j++) {
        const int idx = tid + 256 * j;
        const int slot = idx >> 3, c4 = (idx & 7) * 4;
        const int tl = slot >> 6, rem = slot & 63;
        const int tn = max(t - 4 + tl, 0);
        const int hn = h_base + (rem >> 3), wn = w_base + (rem & 7);
        *(float4*)&KV[slot * KVSTR + c4] =
            *(const float4*)&k[(size_t)((tn * 16 + hn) * 16 + wn) * DMODEL + head * DHEAD + c4];
    }
    __syncthreads();

    // ---- S^T = K @ Q^T : m=320 slots, n=16 tokens, k=32 ----
    uint32_t bf[2][4][2];
    #pragma unroll
    for (int nt = 0; nt < 2; nt++)
        #pragma unroll
        for (int ks = 0; ks < 4; ks++) {
            bf[nt][ks][0] = __float_as_uint(Qsm[(nt * 8 + gr) * KVSTR + ks * 8 + tig]);
            bf[nt][ks][1] = __float_as_uint(Qsm[(nt * 8 + gr) * KVSTR + ks * 8 + 4 + tig]);
        }

    const int nmt = (wp < 4) ? 3 : 2;     // 20 m-tiles over 8 warps
    const int m0s[3] = {wp * 16, (wp + 8) * 16, (wp + 16) * 16};
    float sacc[3][2][4];
    for (int mi = 0; mi < 3; mi++)
        #pragma unroll
        for (int nt = 0; nt < 2; nt++)
            #pragma unroll
            for (int i = 0; i < 4; i++) sacc[mi][nt][i] = 0.f;

    for (int mi = 0; mi < nmt; mi++) {
        const int m0 = m0s[mi];
        #pragma unroll
        for (int ks = 0; ks < 4; ks++) {
            uint32_t a[4];
            a[0] = __float_as_uint(KV[(m0 + gr) * KVSTR + ks * 8 + tig]);
            a[1] = __float_as_uint(KV[(m0 + gr + 8) * KVSTR + ks * 8 + tig]);
            a[2] = __float_as_uint(KV[(m0 + gr) * KVSTR + ks * 8 + 4 + tig]);
            a[3] = __float_as_uint(KV[(m0 + gr + 8) * KVSTR + ks * 8 + 4 + tig]);
            mma_tf32(sacc[mi][0], a, bf[0][ks]);
            mma_tf32(sacc[mi][1], a, bf[1][ks]);
        }
    }

    // ---- mask + scale; per-token partial max ----
    int ho[4], wo[4];
    #pragma unroll
    for (int i = 0; i < 4; i++) {
        const int tk = (i >> 1) * 8 + 2 * tig + (i & 1);
        const int inf = rinfo[tk];
        ho[i] = inf & 15;
        wo[i] = (inf >> 4) & 15;
    }
    float pm[4] = {-INFINITY, -INFINITY, -INFINITY, -INFINITY};
    for (int mi = 0; mi < nmt; mi++) {
        const int s0 = m0s[mi] + gr, s1 = s0 + 8;
        const int tl0 = s0 >> 6, sh0 = (s0 >> 3) & 7, sw0 = s0 & 7;
        const int tl1 = s1 >> 6, sh1 = (s1 >> 3) & 7, sw1 = s1 & 7;
        #pragma unroll
        for (int nt = 0; nt < 2; nt++) {
            #pragma unroll
            for (int ci = 0; ci < 4; ci++) {
                const int pi = nt * 2 + (ci & 1);      // token slot in pm[]
                const int sh = (ci < 2) ? sh0 : sh1;
                const int sw = (ci < 2) ? sw0 : sw1;
                const int tl = (ci < 2) ? tl0 : tl1;
                const bool valid = (tl >= tlmin) &&
                                   ((unsigned)(sh - ho[pi]) <= 4u) &&
                                   ((unsigned)(sw - wo[pi]) <= 4u);
                const float sv = valid ? sacc[mi][nt][ci] * scale : -INFINITY;
                sacc[mi][nt][ci] = sv;
                pm[pi] = fmaxf(pm[pi], sv);
            }
        }
    }
    #pragma unroll
    for (int i = 0; i < 4; i++) {
        pm[i] = fmaxf(pm[i], __shfl_xor_sync(0xffffffffu, pm[i], 4));
        pm[i] = fmaxf(pm[i], __shfl_xor_sync(0xffffffffu, pm[i], 8));
        pm[i] = fmaxf(pm[i], __shfl_xor_sync(0xffffffffu, pm[i], 16));
    }
    if (l < 4) {
        red[(2 * l) * 8 + wp]     = pm[0];
        red[(2 * l + 1) * 8 + wp] = pm[1];
        red[(2 * l + 8) * 8 + wp] = pm[2];
        red[(2 * l + 9) * 8 + wp] = pm[3];
    }
    __syncthreads();
    if (tid < 16) {
        float m = red[tid * 8];
        #pragma unroll
        for (int j = 1; j < 8; j++) m = fmaxf(m, red[tid * 8 + j]);
        Gm[tid] = m;
    }
    __syncthreads();

    // ---- exp, partial sums, write P ----
    float gm[4], ps[4] = {0.f, 0.f, 0.f, 0.f};
    #pragma unroll
    for (int i = 0; i < 4; i++)
        gm[i] = Gm[(i >> 1) * 8 + 2 * tig + (i & 1)];
    for (int mi = 0; mi < nmt; mi++) {
        const int s0 = m0s[mi] + gr, s1 = s0 + 8;
        #pragma unroll
        for (int nt = 0; nt < 2; nt++) {
            const int tk0 = nt * 8 + 2 * tig, tk1 = tk0 + 1;
            const float p0 = __expf(sacc[mi][nt][0] - gm[nt * 2]);
            const float p1 = __expf(sacc[mi][nt][1] - gm[nt * 2 + 1]);
            const float p2 = __expf(sacc[mi][nt][2] - gm[nt * 2]);
            const float p3 = __expf(sacc[mi][nt][3] - gm[nt * 2 + 1]);
            Psm[tk0 * PSTR + s0] = p0;
            Psm[tk1 * PSTR + s0] = p1;
            Psm[tk0 * PSTR + s1] = p2;
            Psm[tk1 * PSTR + s1] = p3;
            ps[nt * 2]     += p0 + p2;
            ps[nt * 2 + 1] += p1 + p3;
        }
    }
    #pragma unroll
    for (int i = 0; i < 4; i++) {
        ps[i] += __shfl_xor_sync(0xffffffffu, ps[i], 4);
        ps[i] += __shfl_xor_sync(0xffffffffu, ps[i], 8);
        ps[i] += __shfl_xor_sync(0xffffffffu, ps[i], 16);
    }
    if (l < 4) {
        red[(2 * l) * 8 + wp]     = ps[0];
        red[(2 * l + 1) * 8 + wp] = ps[1];
        red[(2 * l + 8) * 8 + wp] = ps[2];
        red[(2 * l + 9) * 8 + wp] = ps[3];
    }
    __syncthreads();   // P, sums written; all K reads done

    if (tid < 16) {
        float s = 0.f;
        #pragma unroll
        for (int j = 0; j < 8; j++) s += red[tid * 8 + j];
        Ssum[tid] = s;
    }
    // ---- stage V over K ----
    #pragma unroll
    for (int j = 0; j < 10; j++) {
        const int idx = tid + 256 * j;
        const int slot = idx >> 3, c4 = (idx & 7) * 4;
        const int tl = slot >> 6, rem = slot & 63;
        const int tn = max(t - 4 + tl, 0);
        const int hn = h_base + (rem >> 3), wn = w_base + (rem & 7);
        *(float4*)&KV[slot * KVSTR + c4] =
            *(const float4*)&v[(size_t)((tn * 16 + hn) * 16 + wn) * DMODEL + head * DHEAD + c4];
    }
    __syncthreads();

    // ---- O = P @ V : m=16 tokens, n=32 ch, k=320 (split n0..3 x khalf 0..1) --
    const int ntile = wp & 3, kh = wp >> 2;
    const int n0 = ntile * 8;
    float oacc[4] = {0.f, 0.f, 0.f, 0.f};
    #pragma unroll
    for (int j = 0; j < 20; j++) {
        const int k0 = kh * 160 + j * 8;
        uint32_t a[4], b[2];
        a[0] = __float_as_uint(Psm[gr * PSTR + k0 + tig]);
        a[1] = __float_as_uint(Psm[(gr + 8) * PSTR + k0 + tig]);
        a[2] = __float_as_uint(Psm[gr * PSTR + k0 + 4 + tig]);
        a[3] = __float_as_uint(Psm[(gr + 8) * PSTR + k0 + 4 + tig]);
        b[0] = __float_as_uint(KV[(k0 + tig) * KVSTR + n0 + gr]);
        b[1] = __float_as_uint(KV[(k0 + 4 + tig) * KVSTR + n0 + gr]);
        mma_tf32(oacc, a, b);
    }
    if (wp >= 4)
        *(float4*)&redO[(wp - 4) * 128 + l * 4] =
            make_float4(oacc[0], oacc[1], oacc[2], oacc[3]);
    __syncthreads();
    if (wp < 4) {
        const float4 o2 = *(const float4*)&redO[wp * 128 + l * 4];
        oacc[0] += o2.x; oacc[1] += o2.y; oacc[2] += o2.z; oacc[3] += o2.w;
        const float inv0 = 1.f / Ssum[gr];
        const float inv1 = 1.f / Ssum[gr + 8];
        const int tok0 = rinfo[gr] >> 8;
        const int tok1 = rinfo[gr + 8] >> 8;
        const int col = n0 + 2 * tig;
        *(float2*)&out[(size_t)tok0 * DMODEL + head * DHEAD + col] =
            make_float2(oacc[0] * inv0, oacc[1] * inv0);
        *(float2*)&out[(size_t)tok1 * DMODEL + head * DHEAD + col] =
            make_float2(oacc[2] * inv1, oacc[3] * inv1);
    }
}

// ---------------- launch ------------------------------------------------------
extern "C" void kernel_launch(void* const* d_in, const int* in_sizes, int n_in,
                              void* d_out, int out_size) {
    const float* x   = (const float*)d_in[0];
    const float* n1w = (const float*)d_in[1];
    const float* n2w = (const float*)d_in[2];
    const float* wq  = (const float*)d_in[3];
    const float* bq  = (const float*)d_in[4];
    const float* wk  = (const float*)d_in[5];
    const float* bk  = (const float*)d_in[6];
    const float* wv  = (const float*)d_in[7];
    const float* bv  = (const float*)d_in[8];
    const float* wo  = (const float*)d_in[9];
    const float* bo  = (const float*)d_in[10];
    const float* w1  = (const float*)d_in[11];
    const float* w2  = (const float*)d_in[12];
    const float* w3  = (const float*)d_in[13];
    float* out = (float*)d_out;

    float *p_q, *p_k, *p_v, *p_at, *p_h, *p_fa, *p_rs1, *p_ssp;
    cudaGetSymbolAddress((void**)&p_q,  g_q);
    cudaGetSymbolAddress((void**)&p_k,  g_k);
    cudaGetSymbolAddress((void**)&p_v,  g_v);
    cudaGetSymbolAddress((void**)&p_at, g_at);
    cudaGetSymbolAddress((void**)&p_h,  g_h);
    cudaGetSymbolAddress((void**)&p_fa, g_fa);
    cudaGetSymbolAddress((void**)&p_rs1, g_rs1);
    cudaGetSymbolAddress((void**)&p_ssp, g_ssp);

    const int gate_smem = (DMODEL + 32 + NSTG * 32 * ASTR + 2 * NSTG * 32 * BSTR) * 4;
    const int na_smem = (320 * KVSTR + 16 * PSTR + 16 * KVSTR + 128 + 16 + 16 + 512 + 16) * 4;
    static int configured = 0;
    if (!configured) {
        cudaFuncSetAttribute(gate_v7, cudaFuncAttributeMaxDynamicSharedMemorySize, gate_smem);
        cudaFuncSetAttribute(na3d_v3, cudaFuncAttributeMaxDynamicSharedMemorySize, na_smem);
        configured = 1;
    }

    const dim3 blk(128);

    // 1) rscale1 = rms scale of x
    rms_scale_k<<<NTOK / 8, 256>>>(x, p_rs1);

    // 2) q,k,v = rmsnorm(x) @ {wq,wk,wv} + bias
    gemm_v7<true><<<dim3(DMODEL / 64, NTOK / 32, 3), blk>>>(
        x, p_rs1, n1w, wq, wk, wv, bq, bk, bv, nullptr,
        p_q, p_k, p_v, nullptr, DMODEL, DMODEL);

    // 3) neighborhood attention (tensor-core)
    na3d_v3<<<dim3(128, NHEAD), 256, na_smem>>>(p_q, p_k, p_v, p_at);

    // 4) h = x + attn @ wo + bo   (+ per-row sumsq partials of h)
    gemm_v7<false><<<dim3(DMODEL / 64, NTOK / 32, 1), blk>>>(
        p_at, nullptr, nullptr, wo, nullptr, nullptr, bo, nullptr, nullptr, x,
        p_h, nullptr, nullptr, p_ssp, DMODEL, DMODEL);

    // 5) fa = silu(rmsnorm(h)@w1) * (rmsnorm(h)@w2)
    gate_v7<<<dim3(DFF / 64, NTOK / 32), blk, gate_smem>>>(
        p_h, p_ssp, n2w, w1, w2, p_fa, DFF, DMODEL);

    // 6) out = h + fa @ w3
    gemm_v7<false><<<dim3(DMODEL / 64, NTOK / 32, 1), blk>>>(
        p_fa, nullptr, nullptr, w3, nullptr, nullptr, nullptr, nullptr, nullptr, p_h,
        out, nullptr, nullptr, nullptr, DMODEL, DFF);
}

// round 16
// speedup vs baseline: 1.3132x; 1.0566x over previous
#include <cuda_runtime.h>
#include <math.h>
#include <stdint.h>

#define NTOK   2048
#define DMODEL 256
#define DFF    1024
#define NHEAD  8
#define DHEAD  32
#define KWIN   5
#define NNBR   125   // 5*5*5

// ---------------- scratch (device globals; no allocations allowed) ----------
__device__ float g_q [NTOK * DMODEL];
__device__ float g_k [NTOK * DMODEL];
__device__ float g_v [NTOK * DMODEL];
__device__ float g_at[NTOK * DMODEL];
__device__ float g_h [NTOK * DMODEL];
__device__ float g_fa[NTOK * DFF];
__device__ float g_rs1[NTOK];
__device__ float g_ssp[8 * NTOK];               // per-row sumsq partials of h
__device__ uint32_t g_w1h[(DMODEL / 2) * DFF];  // W1 as bf16, K-paired
__device__ uint32_t g_w2h[(DMODEL / 2) * DFF];  // W2 as bf16, K-paired

// ---------------- helpers ----------------------------------------------------
__device__ __forceinline__ void mma_tf32(float d[4], const uint32_t a[4], const uint32_t b[2]) {
    asm volatile(
        "mma.sync.aligned.m16n8k8.row.col.f32.tf32.tf32.f32 "
        "{%0,%1,%2,%3},{%4,%5,%6,%7},{%8,%9},{%0,%1,%2,%3};"
        : "+f"(d[0]), "+f"(d[1]), "+f"(d[2]), "+f"(d[3])
        : "r"(a[0]), "r"(a[1]), "r"(a[2]), "r"(a[3]), "r"(b[0]), "r"(b[1]));
}

__device__ __forceinline__ void mma_bf16(float d[4], const uint32_t a[4], const uint32_t b[2]) {
    asm volatile(
        "mma.sync.aligned.m16n8k16.row.col.f32.bf16.bf16.f32 "
        "{%0,%1,%2,%3},{%4,%5,%6,%7},{%8,%9},{%0,%1,%2,%3};"
        : "+f"(d[0]), "+f"(d[1]), "+f"(d[2]), "+f"(d[3])
        : "r"(a[0]), "r"(a[1]), "r"(a[2]), "r"(a[3]), "r"(b[0]), "r"(b[1]));
}

__device__ __forceinline__ uint32_t pack_bf16(float lo, float hi) {
    uint32_t r;
    asm("cvt.rn.bf16x2.f32 %0, %1, %2;" : "=r"(r) : "f"(hi), "f"(lo));
    return r;
}

__device__ __forceinline__ void cp_async16(void* smem_dst, const void* gsrc) {
    uint32_t s = (uint32_t)__cvta_generic_to_shared(smem_dst);
    asm volatile("cp.async.cg.shared.global [%0], [%1], 16;" :: "r"(s), "l"(gsrc));
}
__device__ __forceinline__ void cp_commit() { asm volatile("cp.async.commit_group;"); }

#define ASTR 36    // fp32 A frag banks: 4g+tig -> permutation
#define BSTR 72    // fp32 B frag banks: 8tig+g -> permutation
#define NSTG 3     // pipeline stages
#define AH_STR 20  // bf16 A (words/row): banks 20g+tig -> permutation
#define BH_STR 72  // bf16 B (words/kpair-row): banks 8tig+g -> permutation

// ---------------- W1/W2 -> bf16 (K-paired) conversion -------------------------
__global__ __launch_bounds__(256) void cvt_w12_k(
    const float* __restrict__ w1, const float* __restrict__ w2,
    uint32_t* __restrict__ w1h, uint32_t* __restrict__ w2h) {
    const int idx = blockIdx.x * 256 + threadIdx.x;   // (DMODEL/2)*DFF = 131072
    const int kp = idx >> 10, n = idx & 1023;
    const size_t o0 = (size_t)(2 * kp) * DFF + n;
    const size_t o1 = o0 + DFF;
    w1h[idx] = pack_bf16(w1[o0], w1[o1]);
    w2h[idx] = pack_bf16(w2[o0], w2[o1]);
}

// ---------------- RMS scale: one warp per token ------------------------------
__global__ __launch_bounds__(256) void rms_scale_k(const float* __restrict__ x,
                                                   float* __restrict__ rscale) {
    const int warp = threadIdx.x >> 5;
    const int lane = threadIdx.x & 31;
    const int token = blockIdx.x * 8 + warp;
    const float4 a = *(const float4*)&x[(size_t)token * DMODEL + lane * 4];
    const float4 b = *(const float4*)&x[(size_t)token * DMODEL + 128 + lane * 4];
    float s = a.x * a.x + a.y * a.y + a.z * a.z + a.w * a.w
            + b.x * b.x + b.y * b.y + b.z * b.z + b.w * b.w;
    #pragma unroll
    for (int o = 16; o; o >>= 1) s += __shfl_xor_sync(0xffffffffu, s, o);
    if (lane == 0) rscale[token] = rsqrtf(s * (1.0f / DMODEL) + 1e-6f);
}

// ---------------- TF32 GEMM v7: 32x64x32, 128 thr, 3-stage, conflict-free ----
template<bool SCALED>
__global__ __launch_bounds__(128) void gemm_v7(
    const float* __restrict__ A,
    const float* __restrict__ rs, const float* __restrict__ nw,
    const float* __restrict__ B0, const float* __restrict__ B1, const float* __restrict__ B2,
    const float* __restrict__ bias0, const float* __restrict__ bias1, const float* __restrict__ bias2,
    const float* __restrict__ res,
    float* __restrict__ C0, float* __restrict__ C1, float* __restrict__ C2,
    float* __restrict__ ssp,
    int N, int K) {

    const int z = blockIdx.z;
    const float* B    = (z == 0) ? B0    : (z == 1) ? B1    : B2;
    const float* bias = (z == 0) ? bias0 : (z == 1) ? bias1 : bias2;
    float*       C    = (z == 0) ? C0    : (z == 1) ? C1    : C2;

    __shared__ float As[NSTG][32 * ASTR];
    __shared__ float Bs[NSTG][32 * BSTR];
    __shared__ float nws[DMODEL];
    __shared__ float rsc[32];

    const int tid  = threadIdx.x;
    const int warp = tid >> 5;
    const int lane = tid & 31;
    const int g    = lane >> 2;
    const int tig  = lane & 3;
    const int warpRow = (warp & 1) * 16;
    const int warpCol = (warp >> 1) * 32;
    const int bm = blockIdx.y * 32;
    const int bn = blockIdx.x * 64;

    float sc0 = 1.f, sc1 = 1.f;
    if (SCALED) {
        for (int i = tid * 4; i < K; i += 512)
            *(float4*)&nws[i] = *(const float4*)&nw[i];
        if (tid < 32) rsc[tid] = rs[bm + tid];
        __syncthreads();
        sc0 = rsc[warpRow + g];
        sc1 = rsc[warpRow + g + 8];
    }

    float acc[4][4];
    #pragma unroll
    for (int nt = 0; nt < 4; nt++)
        #pragma unroll
        for (int i = 0; i < 4; i++) acc[nt][i] = 0.f;

    const int nkt = K >> 5;

    auto load_tile = [&](int st, int k0) {
        #pragma unroll
        for (int j = 0; j < 2; j++) {
            const int c = tid + 128 * j;
            const int row = c >> 3, kc = (c & 7) * 4;
            cp_async16(&As[st][row * ASTR + kc], &A[(size_t)(bm + row) * K + k0 + kc]);
        }
        #pragma unroll
        for (int j = 0; j < 4; j++) {
            const int c = tid + 128 * j;
            const int row = c >> 4, nc = (c & 15) * 4;
            cp_async16(&Bs[st][row * BSTR + nc], &B[(size_t)(k0 + row) * N + bn + nc]);
        }
        cp_commit();
    };

    load_tile(0, 0);
    load_tile(1, 32);

    for (int kt = 0; kt < nkt; kt++) {
        const int st = kt % NSTG;
        if (kt + 2 < nkt) load_tile((kt + 2) % NSTG, (kt + 2) * 32);
        if (kt + 2 < nkt)      asm volatile("cp.async.wait_group 2;");
        else if (kt + 1 < nkt) asm volatile("cp.async.wait_group 1;");
        else                   asm volatile("cp.async.wait_group 0;");
        __syncthreads();

        const float* Ab = As[st];
        const float* Bb = Bs[st];
        const int kb = kt * 32;
        #pragma unroll
        for (int s = 0; s < 4; s++) {
            const int r0 = warpRow + g;
            float a0 = Ab[r0 * ASTR + 8 * s + tig];
            float a1 = Ab[(r0 + 8) * ASTR + 8 * s + tig];
            float a2 = Ab[r0 * ASTR + 8 * s + 4 + tig];
            float a3 = Ab[(r0 + 8) * ASTR + 8 * s + 4 + tig];
            if (SCALED) {
                const float w0 = nws[kb + 8 * s + tig];
                const float w1 = nws[kb + 8 * s + 4 + tig];
                a0 *= sc0 * w0; a1 *= sc1 * w0; a2 *= sc0 * w1; a3 *= sc1 * w1;
            }
            uint32_t ua[4] = {__float_as_uint(a0), __float_as_uint(a1),
                              __float_as_uint(a2), __float_as_uint(a3)};
            uint32_t b[4][2];
            #pragma unroll
            for (int nt = 0; nt < 4; nt++) {
                const int c = warpCol + nt * 8 + g;
                b[nt][0] = __float_as_uint(Bb[(8 * s + tig) * BSTR + c]);
                b[nt][1] = __float_as_uint(Bb[(8 * s + 4 + tig) * BSTR + c]);
            }
            #pragma unroll
            for (int nt = 0; nt < 4; nt++) mma_tf32(acc[nt], ua, b[nt]);
        }
        __syncthreads();
    }

    const int r0 = bm + warpRow + g;
    const int r1 = r0 + 8;
    float s0 = 0.f, s1 = 0.f;
    #pragma unroll
    for (int nt = 0; nt < 4; nt++) {
        const int col = bn + warpCol + nt * 8 + 2 * tig;
        float b0 = 0.f, b1 = 0.f;
        if (bias) { b0 = bias[col]; b1 = bias[col + 1]; }
        float2 o0 = make_float2(acc[nt][0] + b0, acc[nt][1] + b1);
        float2 o1 = make_float2(acc[nt][2] + b0, acc[nt][3] + b1);
        if (res) {
            const float2 q0 = *(const float2*)&res[(size_t)r0 * N + col];
            const float2 q1 = *(const float2*)&res[(size_t)r1 * N + col];
            o0.x += q0.x; o0.y += q0.y;
            o1.x += q1.x; o1.y += q1.y;
        }
        s0 += o0.x * o0.x + o0.y * o0.y;
        s1 += o1.x * o1.x + o1.y * o1.y;
        *(float2*)&C[(size_t)r0 * N + col] = o0;
        *(float2*)&C[(size_t)r1 * N + col] = o1;
    }
    if (ssp) {
        s0 += __shfl_xor_sync(0xffffffffu, s0, 1);
        s0 += __shfl_xor_sync(0xffffffffu, s0, 2);
        s1 += __shfl_xor_sync(0xffffffffu, s1, 1);
        s1 += __shfl_xor_sync(0xffffffffu, s1, 2);
        if (tig == 0) {
            const int p = blockIdx.x * 2 + (warp >> 1);
            ssp[p * NTOK + r0] = s0;
            ssp[p * NTOK + r1] = s1;
        }
    }
}

// ---------------- gate GEMM bf16: silu(A'@W1)*(A'@W2), m16n8k16 --------------
// A' = rmsnorm(A) packed to bf16 at staging; W1/W2 pre-converted (K-paired).
// 32x64x32 chunks (2 k16-steps each), 128 thr, 3-stage.
__global__ __launch_bounds__(128) void gate_h(
    const float* __restrict__ A,
    const float* __restrict__ ssp, const float* __restrict__ nw,
    const uint32_t* __restrict__ W1h, const uint32_t* __restrict__ W2h,
    float* __restrict__ C, int N, int K) {

    __shared__ float    nws[DMODEL];
    __shared__ float    rsc[32];
    __shared__ uint32_t Ah [NSTG][32 * AH_STR];
    __shared__ uint32_t B1h[NSTG][16 * BH_STR];
    __shared__ uint32_t B2h[NSTG][16 * BH_STR];

    const int tid  = threadIdx.x;
    const int warp = tid >> 5;
    const int lane = tid & 31;
    const int g    = lane >> 2;
    const int tig  = lane & 3;
    const int warpRow = (warp & 1) * 16;
    const int warpCol = (warp >> 1) * 32;
    const int bm = blockIdx.y * 32;
    const int bn = blockIdx.x * 64;

    for (int i = tid * 4; i < K; i += 512)
        *(float4*)&nws[i] = *(const float4*)&nw[i];
    if (tid < 32) {
        const int row = bm + tid;
        float s = 0.f;
        #pragma unroll
        for (int p = 0; p < 8; p++) s += ssp[p * NTOK + row];
        rsc[tid] = rsqrtf(s * (1.0f / DMODEL) + 1e-6f);
    }
    __syncthreads();          // rsc/nws ready before any staging

    float acc1[4][4], acc2[4][4];
    #pragma unroll
    for (int nt = 0; nt < 4; nt++)
        #pragma unroll
        for (int i = 0; i < 4; i++) { acc1[nt][i] = 0.f; acc2[nt][i] = 0.f; }

    const int nkt = K >> 5;

    auto load_tile = [&](int st, int k0) {
        // A: 32 rows x 32 k -> 16 kpairs, scaled+packed (sync path)
        const int arow = tid >> 2;
        const int aq   = tid & 3;
        const float sc = rsc[arow];
        #pragma unroll
        for (int j = 0; j < 2; j++) {
            const int kc = aq * 8 + j * 4;
            const float4 xv = *(const float4*)&A[(size_t)(bm + arow) * K + k0 + kc];
            const float w0 = nws[k0 + kc],     w1 = nws[k0 + kc + 1];
            const float w2 = nws[k0 + kc + 2], w3 = nws[k0 + kc + 3];
            Ah[st][arow * AH_STR + (kc >> 1)]     = pack_bf16(xv.x * sc * w0, xv.y * sc * w1);
            Ah[st][arow * AH_STR + (kc >> 1) + 1] = pack_bf16(xv.z * sc * w2, xv.w * sc * w3);
        }
        // B: 16 kpair-rows x 64 cols of pre-packed bf16 (async)
        const int kp0 = k0 >> 1;
        #pragma unroll
        for (int j = 0; j < 2; j++) {
            const int c = tid + 128 * j;
            const int r = c >> 4, nc4 = (c & 15) * 4;
            const size_t off = (size_t)(kp0 + r) * N + bn + nc4;
            cp_async16(&B1h[st][r * BH_STR + nc4], &W1h[off]);
            cp_async16(&B2h[st][r * BH_STR + nc4], &W2h[off]);
        }
        cp_commit();
    };

    load_tile(0, 0);
    load_tile(1, 32);

    for (int kt = 0; kt < nkt; kt++) {
        const int st = kt % NSTG;
        if (kt + 2 < nkt) load_tile((kt + 2) % NSTG, (kt + 2) * 32);
        if (kt + 2 < nkt)      asm volatile("cp.async.wait_group 2;");
        else if (kt + 1 < nkt) asm volatile("cp.async.wait_group 1;");
        else                   asm volatile("cp.async.wait_group 0;");
        __syncthreads();

        const uint32_t* Ab  = Ah[st];
        const uint32_t* B1b = B1h[st];
        const uint32_t* B2b = B2h[st];
        #pragma unroll
        for (int s = 0; s < 2; s++) {          // two k16-steps per 32-K chunk
            const int r0 = warpRow + g;
            uint32_t a[4];
            a[0] = Ab[r0 * AH_STR + 8 * s + tig];
            a[1] = Ab[(r0 + 8) * AH_STR + 8 * s + tig];
            a[2] = Ab[r0 * AH_STR + 8 * s + 4 + tig];
            a[3] = Ab[(r0 + 8) * AH_STR + 8 * s + 4 + tig];
            uint32_t b1[4][2], b2[4][2];
            #pragma unroll
            for (int nt = 0; nt < 4; nt++) {
                const int c = warpCol + nt * 8 + g;
                b1[nt][0] = B1b[(8 * s + tig) * BH_STR + c];
                b1[nt][1] = B1b[(8 * s + 4 + tig) * BH_STR + c];
                b2[nt][0] = B2b[(8 * s + tig) * BH_STR + c];
                b2[nt][1] = B2b[(8 * s + 4 + tig) * BH_STR + c];
            }
            #pragma unroll
            for (int nt = 0; nt < 4; nt++) {
                mma_bf16(acc1[nt], a, b1[nt]);
                mma_bf16(acc2[nt], a, b2[nt]);
            }
        }
        __syncthreads();
    }

    const int r0 = bm + warpRow + g;
    const int r1 = r0 + 8;
    #pragma unroll
    for (int nt = 0; nt < 4; nt++) {
        const int col = bn + warpCol + nt * 8 + 2 * tig;
        #pragma unroll
        for (int half = 0; half < 2; half++) {
            const int row = (half == 0) ? r0 : r1;
            const float a0 = acc1[nt][half * 2 + 0];
            const float a1 = acc1[nt][half * 2 + 1];
            float2 o;
            o.x = a0 / (1.f + __expf(-a0)) * acc2[nt][half * 2 + 0];
            o.y = a1 / (1.f + __expf(-a1)) * acc2[nt][half * 2 + 1];
            *(float2*)&C[(size_t)row * N + col] = o;
        }
    }
}

// ---------------- NA3D v3: tensor-core attention ------------------------------
#define KVSTR 36
#define PSTR  324

__global__ __launch_bounds__(256) void na3d_v3(
    const float* __restrict__ q, const float* __restrict__ k,
    const float* __restrict__ v, float* __restrict__ out) {

    extern __shared__ float sm[];
    float* KV   = sm;
    float* Psm  = KV + 320 * KVSTR;
    float* Qsm  = Psm + 16 * PSTR;
    float* red  = Qsm + 16 * KVSTR;
    float* Gm   = red + 128;
    float* Ssum = Gm + 16;
    float* redO = Ssum + 16;
    int*  rinfo = (int*)(redO + 512);

    const int tile = blockIdx.x, head = blockIdx.y;
    const int t  = tile >> 4;
    const int th0 = ((tile >> 2) & 3) * 4;
    const int tw0 = (tile & 3) * 4;
    const int h_base = min(max(th0 - 2, 0), 8);
    const int w_base = min(max(tw0 - 2, 0), 8);
    const int tlmin  = max(0, 4 - t);
    const float scale = 0.17677669529663687f;

    const int tid = threadIdx.x;
    const int wp  = tid >> 5;
    const int l   = tid & 31;
    const int gr  = l >> 2;
    const int tig = l & 3;

    if (tid < 16) {
        const int hr = th0 + (tid >> 2), wr = tw0 + (tid & 3);
        const int hoff = min(max(hr - 2, 0), 11) - h_base;
        const int woff = min(max(wr - 2, 0), 11) - w_base;
        const int tok  = (t * 16 + hr) * 16 + wr;
        rinfo[tid] = hoff | (woff << 4) | (tok << 8);
    }
    if (tid < 128) {
        const int r = tid >> 3, c4 = (tid & 7) * 4;
        const int hr = th0 + (r >> 2), wr = tw0 + (r & 3);
        const int tok = (t * 16 + hr) * 16 + wr;
        *(float4*)&Qsm[r * KVSTR + c4] =
            *(const float4*)&q[(size_t)tok * DMODEL + head * DHEAD + c4];
    }
    #pragma unroll
    for (int j = 0; j < 10; j++) {
        const int idx = tid + 256 * j;
        const int slot = idx >> 3, c4 = (idx & 7) * 4;
        const int tl = slot >> 6, rem = slot & 63;
        const int tn = max(t - 4 + tl, 0);
        const int hn = h_base + (rem >> 3), wn = w_base + (rem & 7);
        *(float4*)&KV[slot * KVSTR + c4] =
            *(const float4*)&k[(size_t)((tn * 16 + hn) * 16 + wn) * DMODEL + head * DHEAD + c4];
    }
    __syncthreads();

    uint32_t bf[2][4][2];
    #pragma unroll
    for (int nt = 0; nt < 2; nt++)
        #pragma unroll
        for (int ks = 0; ks < 4; ks++) {
            bf[nt][ks][0] = __float_as_uint(Qsm[(nt * 8 + gr) * KVSTR + ks * 8 + tig]);
            bf[nt][ks][1] = __float_as_uint(Qsm[(nt * 8 + gr) * KVSTR + ks * 8 + 4 + tig]);
        }

    const int nmt = (wp < 4) ? 3 : 2;
    const int m0s[3] = {wp * 16, (wp + 8) * 16, (wp + 16) * 16};
    float sacc[3][2][4];
    for (int mi = 0; mi < 3; mi++)
        #pragma unroll
        for (int nt = 0; nt < 2; nt++)
            #pragma unroll
            for (int i = 0; i < 4; i++) sacc[mi][nt][i] = 0.f;

    for (int mi = 0; mi < nmt; mi++) {
        const int m0 = m0s[mi];
        #pragma unroll
        for (int ks = 0; ks < 4; ks++) {
            uint32_t a[4];
            a[0] = __float_as_uint(KV[(m0 + gr) * KVSTR + ks * 8 + tig]);
            a[1] = __float_as_uint(KV[(m0 + gr + 8) * KVSTR + ks * 8 + tig]);
            a[2] = __float_as_uint(KV[(m0 + gr) * KVSTR + ks * 8 + 4 + tig]);
            a[3] = __float_as_uint(KV[(m0 + gr + 8) * KVSTR + ks * 8 + 4 + tig]);
            mma_tf32(sacc[mi][0], a, bf[0][ks]);
            mma_tf32(sacc[mi][1], a, bf[1][ks]);
        }
    }

    int ho[4], wo[4];
    #pragma unroll
    for (int i = 0; i < 4; i++) {
        const int tk = (i >> 1) * 8 + 2 * tig + (i & 1);
        const int inf = rinfo[tk];
        ho[i] = inf & 15;
        wo[i] = (inf >> 4) & 15;
    }
    float pm[4] = {-INFINITY, -INFINITY, -INFINITY, -INFINITY};
    for (int mi = 0; mi < nmt; mi++) {
        const int s0 = m0s[mi] + gr, s1 = s0 + 8;
        const int tl0 = s0 >> 6, sh0 = (s0 >> 3) & 7, sw0 = s0 & 7;
        const int tl1 = s1 >> 6, sh1 = (s1 >> 3) & 7, sw1 = s1 & 7;
        #pragma unroll
        for (int nt = 0; nt < 2; nt++) {
            #pragma unroll
            for (int ci = 0; ci < 4; ci++) {
                const int pi = nt * 2 + (ci & 1);
                const int sh = (ci < 2) ? sh0 : sh1;
                const int sw = (ci < 2) ? sw0 : sw1;
                const int tl = (ci < 2) ? tl0 : tl1;
                const bool valid = (tl >= tlmin) &&
                                   ((unsigned)(sh - ho[pi]) <= 4u) &&
                                   ((unsigned)(sw - wo[pi]) <= 4u);
                const float sv = valid ? sacc[mi][nt][ci] * scale : -INFINITY;
                sacc[mi][nt][ci] = sv;
                pm[pi] = fmaxf(pm[pi], sv);
            }
        }
    }
    #pragma unroll
    for (int i = 0; i < 4; i++) {
        pm[i] = fmaxf(pm[i], __shfl_xor_sync(0xffffffffu, pm[i], 4));
        pm[i] = fmaxf(pm[i], __shfl_xor_sync(0xffffffffu, pm[i], 8));
        pm[i] = fmaxf(pm[i], __shfl_xor_sync(0xffffffffu, pm[i], 16));
    }
    if (l < 4) {
        red[(2 * l) * 8 + wp]     = pm[0];
        red[(2 * l + 1) * 8 + wp] = pm[1];
        red[(2 * l + 8) * 8 + wp] = pm[2];
        red[(2 * l + 9) * 8 + wp] = pm[3];
    }
    __syncthreads();
    if (tid < 16) {
        float m = red[tid * 8];
        #pragma unroll
        for (int j = 1; j < 8; j++) m = fmaxf(m, red[tid * 8 + j]);
        Gm[tid] = m;
    }
    __syncthreads();

    float gm[4], ps[4] = {0.f, 0.f, 0.f, 0.f};
    #pragma unroll
    for (int i = 0; i < 4; i++)
        gm[i] = Gm[(i >> 1) * 8 + 2 * tig + (i & 1)];
    for (int mi = 0; mi < nmt; mi++) {
        const int s0 = m0s[mi] + gr, s1 = s0 + 8;
        #pragma unroll
        for (int nt = 0; nt < 2; nt++) {
            const int tk0 = nt * 8 + 2 * tig, tk1 = tk0 + 1;
            const float p0 = __expf(sacc[mi][nt][0] - gm[nt * 2]);
            const float p1 = __expf(sacc[mi][nt][1] - gm[nt * 2 + 1]);
            const float p2 = __expf(sacc[mi][nt][2] - gm[nt * 2]);
            const float p3 = __expf(sacc[mi][nt][3] - gm[nt * 2 + 1]);
            Psm[tk0 * PSTR + s0] = p0;
            Psm[tk1 * PSTR + s0] = p1;
            Psm[tk0 * PSTR + s1] = p2;
            Psm[tk1 * PSTR + s1] = p3;
            ps[nt * 2]     += p0 + p2;
            ps[nt * 2 + 1] += p1 + p3;
        }
    }
    #pragma unroll
    for (int i = 0; i < 4; i++) {
        ps[i] += __shfl_xor_sync(0xffffffffu, ps[i], 4);
        ps[i] += __shfl_xor_sync(0xffffffffu, ps[i], 8);
        ps[i] += __shfl_xor_sync(0xffffffffu, ps[i], 16);
    }
    if (l < 4) {
        red[(2 * l) * 8 + wp]     = ps[0];
        red[(2 * l + 1) * 8 + wp] = ps[1];
        red[(2 * l + 8) * 8 + wp] = ps[2];
        red[(2 * l + 9) * 8 + wp] = ps[3];
    }
    __syncthreads();

    if (tid < 16) {
        float s = 0.f;
        #pragma unroll
        for (int j = 0; j < 8; j++) s += red[tid * 8 + j];
        Ssum[tid] = s;
    }
    #pragma unroll
    for (int j = 0; j < 10; j++) {
        const int idx = tid + 256 * j;
        const int slot = idx >> 3, c4 = (idx & 7) * 4;
        const int tl = slot >> 6, rem = slot & 63;
        const int tn = max(t - 4 + tl, 0);
        const int hn = h_base + (rem >> 3), wn = w_base + (rem & 7);
        *(float4*)&KV[slot * KVSTR + c4] =
            *(const float4*)&v[(size_t)((tn * 16 + hn) * 16 + wn) * DMODEL + head * DHEAD + c4];
    }
    __syncthreads();

    const int ntile = wp & 3, kh = wp >> 2;
    const int n0 = ntile * 8;
    float oacc[4] = {0.f, 0.f, 0.f, 0.f};
    #pragma unroll
    for (int j = 0; j < 20; j++) {
        const int k0 = kh * 160 + j * 8;
        uint32_t a[4], b[2];
        a[0] = __float_as_uint(Psm[gr * PSTR + k0 + tig]);
        a[1] = __float_as_uint(Psm[(gr + 8) * PSTR + k0 + tig]);
        a[2] = __float_as_uint(Psm[gr * PSTR + k0 + 4 + tig]);
        a[3] = __float_as_uint(Psm[(gr + 8) * PSTR + k0 + 4 + tig]);
        b[0] = __float_as_uint(KV[(k0 + tig) * KVSTR + n0 + gr]);
        b[1] = __float_as_uint(KV[(k0 + 4 + tig) * KVSTR + n0 + gr]);
        mma_tf32(oacc, a, b);
    }
    if (wp >= 4)
        *(float4*)&redO[(wp - 4) * 128 + l * 4] =
            make_float4(oacc[0], oacc[1], oacc[2], oacc[3]);
    __syncthreads();
    if (wp < 4) {
        const float4 o2 = *(const float4*)&redO[wp * 128 + l * 4];
        oacc[0] += o2.x; oacc[1] += o2.y; oacc[2] += o2.z; oacc[3] += o2.w;
        const float inv0 = 1.f / Ssum[gr];
        const float inv1 = 1.f / Ssum[gr + 8];
        const int tok0 = rinfo[gr] >> 8;
        const int tok1 = rinfo[gr + 8] >> 8;
        const int col = n0 + 2 * tig;
        *(float2*)&out[(size_t)tok0 * DMODEL + head * DHEAD + col] =
            make_float2(oacc[0] * inv0, oacc[1] * inv0);
        *(float2*)&out[(size_t)tok1 * DMODEL + head * DHEAD + col] =
            make_float2(oacc[2] * inv1, oacc[3] * inv1);
    }
}

// ---------------- launch ------------------------------------------------------
extern "C" void kernel_launch(void* const* d_in, const int* in_sizes, int n_in,
                              void* d_out, int out_size) {
    const float* x   = (const float*)d_in[0];
    const float* n1w = (const float*)d_in[1];
    const float* n2w = (const float*)d_in[2];
    const float* wq  = (const float*)d_in[3];
    const float* bq  = (const float*)d_in[4];
    const float* wk  = (const float*)d_in[5];
    const float* bk  = (const float*)d_in[6];
    const float* wv  = (const float*)d_in[7];
    const float* bv  = (const float*)d_in[8];
    const float* wo  = (const float*)d_in[9];
    const float* bo  = (const float*)d_in[10];
    const float* w1  = (const float*)d_in[11];
    const float* w2  = (const float*)d_in[12];
    const float* w3  = (const float*)d_in[13];
    float* out = (float*)d_out;

    float *p_q, *p_k, *p_v, *p_at, *p_h, *p_fa, *p_rs1, *p_ssp;
    uint32_t *p_w1h, *p_w2h;
    cudaGetSymbolAddress((void**)&p_q,  g_q);
    cudaGetSymbolAddress((void**)&p_k,  g_k);
    cudaGetSymbolAddress((void**)&p_v,  g_v);
    cudaGetSymbolAddress((void**)&p_at, g_at);
    cudaGetSymbolAddress((void**)&p_h,  g_h);
    cudaGetSymbolAddress((void**)&p_fa, g_fa);
    cudaGetSymbolAddress((void**)&p_rs1, g_rs1);
    cudaGetSymbolAddress((void**)&p_ssp, g_ssp);
    cudaGetSymbolAddress((void**)&p_w1h, g_w1h);
    cudaGetSymbolAddress((void**)&p_w2h, g_w2h);

    const int na_smem = (320 * KVSTR + 16 * PSTR + 16 * KVSTR + 128 + 16 + 16 + 512 + 16) * 4;
    static int configured = 0;
    if (!configured) {
        cudaFuncSetAttribute(na3d_v3, cudaFuncAttributeMaxDynamicSharedMemorySize, na_smem);
        configured = 1;
    }

    const dim3 blk(128);

    // 0) convert W1/W2 to bf16 (K-paired); independent of everything else
    cvt_w12_k<<<(DMODEL / 2) * DFF / 256, 256>>>(w1, w2, p_w1h, p_w2h);

    // 1) rscale1 = rms scale of x
    rms_scale_k<<<NTOK / 8, 256>>>(x, p_rs1);

    // 2) q,k,v = rmsnorm(x) @ {wq,wk,wv} + bias
    gemm_v7<true><<<dim3(DMODEL / 64, NTOK / 32, 3), blk>>>(
        x, p_rs1, n1w, wq, wk, wv, bq, bk, bv, nullptr,
        p_q, p_k, p_v, nullptr, DMODEL, DMODEL);

    // 3) neighborhood attention (tensor-core)
    na3d_v3<<<dim3(128, NHEAD), 256, na_smem>>>(p_q, p_k, p_v, p_at);

    // 4) h = x + attn @ wo + bo   (+ per-row sumsq partials of h)
    gemm_v7<false><<<dim3(DMODEL / 64, NTOK / 32, 1), blk>>>(
        p_at, nullptr, nullptr, wo, nullptr, nullptr, bo, nullptr, nullptr, x,
        p_h, nullptr, nullptr, p_ssp, DMODEL, DMODEL);

    // 5) fa = silu(rmsnorm(h)@w1) * (rmsnorm(h)@w2)   (bf16 MMA)
    gate_h<<<dim3(DFF / 64, NTOK / 32), blk>>>(
        p_h, p_ssp, n2w, p_w1h, p_w2h, p_fa, DFF, DMODEL);

    // 6) out = h + fa @ w3
    gemm_v7<false><<<dim3(DMODEL / 64, NTOK / 32, 1), blk>>>(
        p_fa, nullptr, nullptr, w3, nullptr, nullptr, nullptr, nullptr, nullptr, p_h,
        out, nullptr, nullptr, nullptr, DMODEL, DFF);
}